// round 5
// baseline (speedup 1.0000x reference)
#include <cuda_runtime.h>
#include <cuda_bf16.h>
#include <cstdint>

#define DIM     256
#define BT      32768
#define NCODE   2048
#define MARGIN  1.0f
#define CAP     24
#define M_CTA   256
#define N_TILE  128
#define N_TILES (NCODE / N_TILE)   // 16

// smem layout (relative to 1KB-aligned base)
#define OFF_A    0                 // 256 x 256 bf16 = 128 KB (4 planes x 32KB)
#define OFF_B    131072            // 2 half-K stages x 32 KB
#define OFF_KEY  196608            // u32[256]
#define OFF_CNT  197632            // int[256]
#define OFF_CAND 198656            // int[256][CAP] = 24576
#define SMEM_BYTES (198656 + 256 * CAP * 4 + 1024)

// ---------------------------------------------------------------------------
__device__ __nv_bfloat16 g_cbb[(size_t)NCODE * DIM];   // 1 MB
__device__ float g_c2[NCODE];
__device__ int   g_flag[BT];
__device__ float g_partial[BT];
__device__ float g_dummy[BT + 1];

// ---------------------------------------------------------------------------
__device__ __forceinline__ uint32_t smem_u32(const void* p) {
    uint32_t a;
    asm("{ .reg .u64 t; cvta.to.shared.u64 t, %1; cvt.u32.u64 %0, t; }"
        : "=r"(a) : "l"(p));
    return a;
}

#define SWZ(o) ((o) ^ (((o) >> 3) & 0x70))

__device__ __forceinline__ void cp16(uint32_t d, const void* s) {
    asm volatile("cp.async.cg.shared.global [%0], [%1], 16;\n"
                 :: "r"(d), "l"(__cvta_generic_to_global(s)));
}
__device__ __forceinline__ void cp_commit() {
    asm volatile("cp.async.commit_group;\n" ::: "memory");
}
template <int N> __device__ __forceinline__ void cp_wait() {
    asm volatile("cp.async.wait_group %0;\n" :: "n"(N) : "memory");
}

__device__ __forceinline__ void ldm_x4(uint32_t& r0, uint32_t& r1,
                                       uint32_t& r2, uint32_t& r3, uint32_t a) {
    asm volatile("ldmatrix.sync.aligned.m8n8.x4.shared.b16 {%0,%1,%2,%3}, [%4];"
                 : "=r"(r0), "=r"(r1), "=r"(r2), "=r"(r3) : "r"(a));
}

__device__ __forceinline__ void mma_bf16(float* d, uint32_t a0, uint32_t a1,
                                         uint32_t a2, uint32_t a3,
                                         uint32_t b0, uint32_t b1) {
    asm volatile(
        "mma.sync.aligned.m16n8k16.row.col.f32.bf16.bf16.f32 "
        "{%0,%1,%2,%3}, {%4,%5,%6,%7}, {%8,%9}, {%0,%1,%2,%3};"
        : "+f"(d[0]), "+f"(d[1]), "+f"(d[2]), "+f"(d[3])
        : "r"(a0), "r"(a1), "r"(a2), "r"(a3), "r"(b0), "r"(b1));
}

__device__ __forceinline__ uint32_t fkey(float f) {
    uint32_t u = __float_as_uint(f);
    return (u & 0x80000000u) ? ~u : (u | 0x80000000u);
}
__device__ __forceinline__ float fdec(uint32_t k) {
    uint32_t u = (k & 0x80000000u) ? (k ^ 0x80000000u) : ~k;
    return __uint_as_float(u);
}

// ---------------------------------------------------------------------------
__global__ void tobf16_kernel(const float* __restrict__ in,
                              __nv_bfloat16* __restrict__ outp, int n4) {
    int i = blockIdx.x * blockDim.x + threadIdx.x;
    if (i >= n4) return;
    float4 v = ((const float4*)in)[i];
    ((__nv_bfloat162*)outp)[2 * i]     = __floats2bfloat162_rn(v.x, v.y);
    ((__nv_bfloat162*)outp)[2 * i + 1] = __floats2bfloat162_rn(v.z, v.w);
}

__global__ void c2_kernel(const float* __restrict__ cb, int N) {
    int warp = (blockIdx.x * blockDim.x + threadIdx.x) >> 5;
    int lane = threadIdx.x & 31;
    if (warp >= N) return;
    const float4* row = (const float4*)(cb + (size_t)warp * DIM);
    float s = 0.f;
#pragma unroll
    for (int i = 0; i < 2; i++) {
        float4 v = row[lane + i * 32];
        s += v.x * v.x + v.y * v.y + v.z * v.z + v.w * v.w;
    }
#pragma unroll
    for (int o = 16; o > 0; o >>= 1) s += __shfl_xor_sync(0xffffffffu, s, o);
    if (lane == 0) g_c2[warp] = s;
}

// ---------------------------------------------------------------------------
// stage one 32KB half-K B chunk: 128 codes x 128 dims bf16
// ---------------------------------------------------------------------------
__device__ __forceinline__ void stage_b(uint32_t dst, int n0, int kh, int tid) {
#pragma unroll
    for (int i = 0; i < 4; i++) {
        int idx   = tid + (i << 9);        // 0..2047
        int c16   = idx & 7;
        int plane = (idx >> 3) & 1;
        int row   = idx >> 4;
        cp16(dst + plane * 16384 + SWZ((uint32_t)(row * 128 + c16 * 16)),
             g_cbb + (size_t)(n0 + row) * DIM + kh * 128 + plane * 64 + c16 * 8);
    }
    cp_commit();
}

// ---------------------------------------------------------------------------
// Main fused kernel: 512 threads, 16 warps (4M x 4N), warp tile 64x32.
// CTA tile M=256 x full N=2048 (16 n-tiles), K=256. A resident; B half-K
// double-buffered. Margin-band candidates -> exact fp32 rescore -> gather.
// ---------------------------------------------------------------------------
__global__ void __launch_bounds__(512, 1)
vq_main_kernel(const float* __restrict__ x, const float* __restrict__ cb,
               float* __restrict__ out_q, float* __restrict__ out_idx) {
    extern __shared__ char smraw[];
    const uint32_t sb0   = smem_u32(smraw);
    const uint32_t sbase = (sb0 + 1023) & ~1023u;
    char* smp = smraw + (sbase - sb0);

    uint32_t* rowkey = (uint32_t*)(smp + OFF_KEY);
    int*      cnt    = (int*)     (smp + OFF_CNT);
    int*      cand   = (int*)     (smp + OFF_CAND);

    const int tid  = threadIdx.x;
    const int wid  = tid >> 5;
    const int lane = tid & 31;
    const int m0   = blockIdx.x * M_CTA;
    const int wm   = (wid & 3) * 64;
    const int wn   = (wid >> 2) * 32;
    const int lrow = lane & 15;
    const int lcol = (lane >> 4) << 4;
    const int g    = lane >> 2;
    const int tg   = lane & 3;

    if (tid < 256) { rowkey[tid] = 0xFFFFFFFFu; cnt[tid] = 0; }

    // ---- Stage A: 256 x 256 fp32 -> bf16, 4 swizzled 32KB K-planes --------
#pragma unroll
    for (int i = 0; i < 32; i++) {
        int f   = tid + (i << 9);          // 0..16383 float4s
        int row = f >> 6;
        int c4  = f & 63;
        float4 v = ((const float4*)(x + (size_t)(m0 + row) * DIM))[c4];
        __nv_bfloat162 p0 = __floats2bfloat162_rn(v.x, v.y);
        __nv_bfloat162 p1 = __floats2bfloat162_rn(v.z, v.w);
        int plane = c4 >> 4;
        uint32_t off = SWZ((uint32_t)(row * 128 + (c4 & 15) * 8));
        *(uint2*)(smp + OFF_A + plane * 32768 + off) =
            make_uint2(*(uint32_t*)&p0, *(uint32_t*)&p1);
    }

    stage_b(sbase + OFF_B, 0, 0, tid);   // stage s=0

    float acc[4][4][4];

    for (int s = 0; s < 2 * N_TILES; s++) {
        const int nt = s >> 1;
        const int kh = s & 1;
        const int n0 = nt * N_TILE;

        cp_wait<0>();
        __syncthreads();   // stage s ready; all prior-buffer reads done

        if (s + 1 < 2 * N_TILES) {
            const int s1 = s + 1;
            stage_b(sbase + OFF_B + (s1 & 1) * 32768,
                    (s1 >> 1) * N_TILE, s1 & 1, tid);
        }

        if (kh == 0) {
#pragma unroll
            for (int a = 0; a < 4; a++)
#pragma unroll
                for (int b = 0; b < 4; b++)
#pragma unroll
                    for (int c = 0; c < 4; c++) acc[a][b][c] = 0.f;
        }

        const uint32_t sB = sbase + OFF_B + (s & 1) * 32768;
#pragma unroll
        for (int ks = 0; ks < 8; ks++) {
            const uint32_t pa = sbase + OFF_A + (kh * 2 + (ks >> 2)) * 32768;
            const uint32_t pb = sB + (ks >> 2) * 16384;
            const int kb = (ks & 3) * 32 + lcol;
            uint32_t a[4][4], b0[4], b1[4];
#pragma unroll
            for (int im = 0; im < 4; im++)
                ldm_x4(a[im][0], a[im][1], a[im][2], a[im][3],
                       pa + SWZ((uint32_t)((wm + im * 16 + lrow) * 128 + kb)));
            ldm_x4(b0[0], b0[1], b0[2], b0[3],
                   pb + SWZ((uint32_t)((wn + lrow) * 128 + kb)));
            ldm_x4(b1[0], b1[1], b1[2], b1[3],
                   pb + SWZ((uint32_t)((wn + 16 + lrow) * 128 + kb)));
#pragma unroll
            for (int im = 0; im < 4; im++) {
                mma_bf16(acc[im][0], a[im][0], a[im][1], a[im][2], a[im][3], b0[0], b0[2]);
                mma_bf16(acc[im][1], a[im][0], a[im][1], a[im][2], a[im][3], b0[1], b0[3]);
                mma_bf16(acc[im][2], a[im][0], a[im][1], a[im][2], a[im][3], b1[0], b1[2]);
                mma_bf16(acc[im][3], a[im][0], a[im][1], a[im][2], a[im][3], b1[1], b1[3]);
            }
        }

        if (kh == 1) {
            // ---- Epilogue: running min (tg-reduced) + candidate collect ----
            float c2r[4][2];
#pragma unroll
            for (int jn = 0; jn < 4; jn++)
#pragma unroll
                for (int q = 0; q < 2; q++)
                    c2r[jn][q] = __ldg(&g_c2[n0 + wn + jn * 8 + tg * 2 + q]);

#pragma unroll
            for (int im = 0; im < 4; im++)
#pragma unroll
                for (int h = 0; h < 2; h++) {
                    int r = wm + im * 16 + h * 8 + g;
                    float mn = 3.4e38f;
#pragma unroll
                    for (int jn = 0; jn < 4; jn++)
#pragma unroll
                        for (int q = 0; q < 2; q++)
                            mn = fminf(mn, fmaf(-2.f, acc[im][jn][h * 2 + q],
                                                c2r[jn][q]));
                    mn = fminf(mn, __shfl_xor_sync(0xffffffffu, mn, 1));
                    mn = fminf(mn, __shfl_xor_sync(0xffffffffu, mn, 2));
                    if (tg == 0) atomicMin(&rowkey[r], fkey(mn));
                }
            __syncthreads();

#pragma unroll
            for (int im = 0; im < 4; im++)
#pragma unroll
                for (int h = 0; h < 2; h++) {
                    int r = wm + im * 16 + h * 8 + g;
                    float thr = fdec(rowkey[r]) + MARGIN;
#pragma unroll
                    for (int jn = 0; jn < 4; jn++)
#pragma unroll
                        for (int q = 0; q < 2; q++) {
                            float sc = fmaf(-2.f, acc[im][jn][h * 2 + q],
                                            c2r[jn][q]);
                            if (sc < thr) {
                                int p = atomicAdd(&cnt[r], 1);
                                if (p < CAP)
                                    cand[r * CAP + p] =
                                        n0 + wn + jn * 8 + tg * 2 + q;
                            }
                        }
                }
            // no trailing sync: later updates only shrink false-positive set
        }
    }

    __syncthreads();

    // ---- Exact fp32 rescore + gather + SSE partial (1 warp per row) -------
    for (int r = wid; r < M_CTA; r += 16) {
        const int row = m0 + r;
        const int c = cnt[r];
        const bool ovf = (c > CAP);
        if (lane == 0) g_flag[row] = ovf ? 1 : 0;
        if (ovf) continue;

        const float4* xr = (const float4*)(x + (size_t)row * DIM);
        float4 xv0 = xr[lane * 2], xv1 = xr[lane * 2 + 1];

        float bv = 3.4e38f;
        int   bi = 0x7fffffff;
        for (int ci = 0; ci < c; ci++) {
            int n = cand[r * CAP + ci];
            const float4* cr = (const float4*)(cb + (size_t)n * DIM);
            float4 c0 = cr[lane * 2], c1 = cr[lane * 2 + 1];
            float dot = xv0.x * c0.x + xv0.y * c0.y + xv0.z * c0.z + xv0.w * c0.w
                      + xv1.x * c1.x + xv1.y * c1.y + xv1.z * c1.z + xv1.w * c1.w;
#pragma unroll
            for (int o = 16; o > 0; o >>= 1)
                dot += __shfl_xor_sync(0xffffffffu, dot, o);
            float sv = __ldg(&g_c2[n]) - 2.f * dot;
            if (sv < bv || (sv == bv && n < bi)) { bv = sv; bi = n; }
        }

        const float4* cr = (const float4*)(cb + (size_t)bi * DIM);
        float4 c0 = cr[lane * 2], c1 = cr[lane * 2 + 1];
        float4* qr = (float4*)(out_q + (size_t)row * DIM);
        qr[lane * 2]     = c0;
        qr[lane * 2 + 1] = c1;

        float dx = xv0.x - c0.x, dy = xv0.y - c0.y, dz = xv0.z - c0.z, dw = xv0.w - c0.w;
        float d = dx * dx + dy * dy + dz * dz + dw * dw;
        dx = xv1.x - c1.x; dy = xv1.y - c1.y; dz = xv1.z - c1.z; dw = xv1.w - c1.w;
        d += dx * dx + dy * dy + dz * dz + dw * dw;
#pragma unroll
        for (int o = 16; o > 0; o >>= 1) d += __shfl_xor_sync(0xffffffffu, d, o);
        if (lane == 0) {
            g_partial[row] = d;
            out_idx[row]   = (float)bi;
        }
    }
}

// ---------------------------------------------------------------------------
// Rescue: full exact rescan for overflowed rows (rare), fused gather+partial.
// ---------------------------------------------------------------------------
__global__ void __launch_bounds__(1024)
rescue_kernel(const float* __restrict__ x, const float* __restrict__ cb,
              float* __restrict__ out_q, float* __restrict__ out_idx, int N) {
    const int wid = threadIdx.x >> 5, lane = threadIdx.x & 31;
    const int t = blockIdx.x * 32 + wid;
    if (g_flag[t] == 0) return;

    const float4* xr = (const float4*)(x + (size_t)t * DIM);
    float4 xv0 = xr[lane * 2], xv1 = xr[lane * 2 + 1];

    float bv = 3.4e38f;
    int   bi = 0x7fffffff;
    for (int n = 0; n < N; n++) {
        const float4* cr = (const float4*)(cb + (size_t)n * DIM);
        float4 c0 = cr[lane * 2], c1 = cr[lane * 2 + 1];
        float dot = xv0.x * c0.x + xv0.y * c0.y + xv0.z * c0.z + xv0.w * c0.w
                  + xv1.x * c1.x + xv1.y * c1.y + xv1.z * c1.z + xv1.w * c1.w;
#pragma unroll
        for (int o = 16; o > 0; o >>= 1)
            dot += __shfl_xor_sync(0xffffffffu, dot, o);
        float s = __ldg(&g_c2[n]) - 2.f * dot;
        if (s < bv || (s == bv && n < bi)) { bv = s; bi = n; }
    }

    const float4* cr = (const float4*)(cb + (size_t)bi * DIM);
    float4 c0 = cr[lane * 2], c1 = cr[lane * 2 + 1];
    float4* qr = (float4*)(out_q + (size_t)t * DIM);
    qr[lane * 2]     = c0;
    qr[lane * 2 + 1] = c1;

    float dx = xv0.x - c0.x, dy = xv0.y - c0.y, dz = xv0.z - c0.z, dw = xv0.w - c0.w;
    float d = dx * dx + dy * dy + dz * dz + dw * dw;
    dx = xv1.x - c1.x; dy = xv1.y - c1.y; dz = xv1.z - c1.z; dw = xv1.w - c1.w;
    d += dx * dx + dy * dy + dz * dz + dw * dw;
#pragma unroll
    for (int o = 16; o > 0; o >>= 1) d += __shfl_xor_sync(0xffffffffu, d, o);
    if (lane == 0) {
        g_partial[t] = d;
        out_idx[t]   = (float)bi;
    }
}

// ---------------------------------------------------------------------------
__global__ void loss_kernel(float* __restrict__ out_loss, int n4, float inv_count) {
    __shared__ float red[32];
    const int tid = threadIdx.x;
    float s = 0.f;
    const float4* p4 = (const float4*)g_partial;
    for (int i = tid; i < n4; i += 1024) {
        float4 v = p4[i];
        s += v.x + v.y + v.z + v.w;
    }
#pragma unroll
    for (int o = 16; o > 0; o >>= 1) s += __shfl_xor_sync(0xffffffffu, s, o);
    if ((tid & 31) == 0) red[tid >> 5] = s;
    __syncthreads();
    if (tid < 32) {
        float v = red[tid];
#pragma unroll
        for (int o = 16; o > 0; o >>= 1) v += __shfl_xor_sync(0xffffffffu, v, o);
        if (tid == 0) *out_loss = 2.f * v * inv_count;
    }
}

// ---------------------------------------------------------------------------
extern "C" void kernel_launch(void* const* d_in, const int* in_sizes, int n_in,
                              void* d_out, int out_size) {
    const float* x  = (const float*)d_in[0];
    const float* cb = (const float*)d_in[1];
    float* out = (float*)d_out;

    const int bt = in_sizes[0] / DIM;   // 32768
    const int nc = in_sizes[1] / DIM;   // 2048

    const long long need = (long long)bt * DIM + bt + 1;
    const bool full_layout = ((long long)out_size >= need);
    float* out_idx  = full_layout ? (out + (size_t)bt * DIM) : g_dummy;
    float* out_loss = full_layout ? (out + (size_t)bt * DIM + bt) : (g_dummy + BT);

    __nv_bfloat16* cbb;
    cudaGetSymbolAddress((void**)&cbb, g_cbb);

    const int nc4 = nc * DIM / 4;
    tobf16_kernel<<<(nc4 + 255) / 256, 256>>>(cb, cbb, nc4);
    c2_kernel<<<(nc + 7) / 8, 256>>>(cb, nc);

    cudaFuncSetAttribute(vq_main_kernel,
                         cudaFuncAttributeMaxDynamicSharedMemorySize, SMEM_BYTES);
    vq_main_kernel<<<bt / M_CTA, 512, SMEM_BYTES>>>(x, cb, out, out_idx);

    rescue_kernel<<<bt / 32, 1024>>>(x, cb, out, out_idx, nc);
    loss_kernel<<<1, 1024>>>(out_loss, bt / 4, 1.f / ((float)bt * (float)DIM));
}